// round 1
// baseline (speedup 1.0000x reference)
#include <cuda_runtime.h>
#include <cuda_bf16.h>
#include <math.h>

// ---------------------------------------------------------------------------
// HierarchicalClustering: 3 levels of
//   logits = 0.5*(h @ c^T) - 0.25*||c||^2   (||h||^2 cancels in softmax)
//   p      = softmax_rows(logits)
//   t      = tanh(h @ W^T + b)
//   h_next = p^T @ t
// Shapes: h0 [16384,1024]; centers {2048,256,32}x1024; W 1024x1024.
// ---------------------------------------------------------------------------

#define D 1024
#define N0 16384
#define N1 2048
#define N2 256
#define N3 32

// Scratch (device globals; no allocation allowed)
__device__ float g_G[(size_t)N0 * N1];   // Gram / p buffer (max 16384x2048)
__device__ float g_T[(size_t)N0 * D];    // tanh buffer (max 16384x1024)
__device__ float g_cn[N1];               // center norms (max 2048)
__device__ float g_H1[(size_t)N1 * D];
__device__ float g_H2[(size_t)N2 * D];

// ---------------------------------------------------------------------------
// Tiled SGEMM, NT variant: C[M,N] = A[M,K] * B[N,K]^T  (dot of rows)
// EPI=0: plain store.  EPI=1: C = tanhf(acc + bias[col])
// BM=BN=128, BK=16, 256 threads, 8x8 per thread.
// Assumes: K % 16 == 0, M % 4 == 0, N % 4 == 0 (guards handle M,N < tile).
// ---------------------------------------------------------------------------
#define BM 128
#define BN 128
#define BK 16

template <int EPI>
__global__ __launch_bounds__(256)
void gemm_nt(const float* __restrict__ A, const float* __restrict__ B,
             const float* __restrict__ bias, float* __restrict__ C,
             int M, int N, int K)
{
    __shared__ float As[BK][BM + 4];
    __shared__ float Bs[BK][BN + 4];

    const int bm = blockIdx.y * BM;
    const int bn = blockIdx.x * BN;
    const int tid = threadIdx.x;
    const int tx = tid & 15;        // 0..15  -> N direction (8 cols each)
    const int ty = tid >> 4;        // 0..15  -> M direction (8 rows each)

    float acc[8][8];
#pragma unroll
    for (int i = 0; i < 8; i++)
#pragma unroll
        for (int j = 0; j < 8; j++) acc[i][j] = 0.f;

    for (int k0 = 0; k0 < K; k0 += BK) {
        // Load A tile: BM x BK  (512 float4, 2 per thread)
#pragma unroll
        for (int it = 0; it < 2; it++) {
            int idx = tid + it * 256;
            int r = idx >> 2, c4 = (idx & 3) << 2;
            float4 v = make_float4(0.f, 0.f, 0.f, 0.f);
            int gr = bm + r;
            if (gr < M) v = *(const float4*)&A[(size_t)gr * K + k0 + c4];
            As[c4 + 0][r] = v.x; As[c4 + 1][r] = v.y;
            As[c4 + 2][r] = v.z; As[c4 + 3][r] = v.w;
        }
        // Load B tile: BN x BK
#pragma unroll
        for (int it = 0; it < 2; it++) {
            int idx = tid + it * 256;
            int r = idx >> 2, c4 = (idx & 3) << 2;
            float4 v = make_float4(0.f, 0.f, 0.f, 0.f);
            int gr = bn + r;
            if (gr < N) v = *(const float4*)&B[(size_t)gr * K + k0 + c4];
            Bs[c4 + 0][r] = v.x; Bs[c4 + 1][r] = v.y;
            Bs[c4 + 2][r] = v.z; Bs[c4 + 3][r] = v.w;
        }
        __syncthreads();

#pragma unroll
        for (int k = 0; k < BK; k++) {
            float a[8], b[8];
            *(float4*)&a[0] = *(const float4*)&As[k][ty * 8 + 0];
            *(float4*)&a[4] = *(const float4*)&As[k][ty * 8 + 4];
            *(float4*)&b[0] = *(const float4*)&Bs[k][tx * 8 + 0];
            *(float4*)&b[4] = *(const float4*)&Bs[k][tx * 8 + 4];
#pragma unroll
            for (int i = 0; i < 8; i++)
#pragma unroll
                for (int j = 0; j < 8; j++) acc[i][j] = fmaf(a[i], b[j], acc[i][j]);
        }
        __syncthreads();
    }

    // Epilogue
#pragma unroll
    for (int i = 0; i < 8; i++) {
        int row = bm + ty * 8 + i;
        if (row >= M) continue;
#pragma unroll
        for (int j4 = 0; j4 < 2; j4++) {
            int col = bn + tx * 8 + j4 * 4;
            if (col >= N) continue;
            float4 v;
            float* av = &acc[i][j4 * 4];
            if (EPI == 1) {
                v.x = tanhf(av[0] + bias[col + 0]);
                v.y = tanhf(av[1] + bias[col + 1]);
                v.z = tanhf(av[2] + bias[col + 2]);
                v.w = tanhf(av[3] + bias[col + 3]);
            } else {
                v.x = av[0]; v.y = av[1]; v.z = av[2]; v.w = av[3];
            }
            *(float4*)&C[(size_t)row * N + col] = v;
        }
    }
}

// ---------------------------------------------------------------------------
// Tiled SGEMM, TN variant: C[M,N] = A[K,M]^T * B[K,N]
// (A = p stored [n_prev, n_cur], B = t stored [n_prev, 1024])
// Assumes K % 16 == 0, N % 128 == 0, M % 4 == 0.
// ---------------------------------------------------------------------------
__global__ __launch_bounds__(256)
void gemm_tn(const float* __restrict__ A, const float* __restrict__ B,
             float* __restrict__ C, int M, int N, int K)
{
    __shared__ float As[BK][BM + 4];
    __shared__ float Bs[BK][BN + 4];

    const int bm = blockIdx.y * BM;
    const int bn = blockIdx.x * BN;
    const int tid = threadIdx.x;
    const int tx = tid & 15;
    const int ty = tid >> 4;

    float acc[8][8];
#pragma unroll
    for (int i = 0; i < 8; i++)
#pragma unroll
        for (int j = 0; j < 8; j++) acc[i][j] = 0.f;

    for (int k0 = 0; k0 < K; k0 += BK) {
        // A tile: BK rows x BM cols of A[K,M]  (512 float4)
#pragma unroll
        for (int it = 0; it < 2; it++) {
            int idx = tid + it * 256;
            int r = idx >> 5, c4 = (idx & 31) << 2;
            float4 v = make_float4(0.f, 0.f, 0.f, 0.f);
            if (bm + c4 < M) v = *(const float4*)&A[(size_t)(k0 + r) * M + bm + c4];
            *(float4*)&As[r][c4] = v;
        }
        // B tile: BK rows x BN cols of B[K,N]
#pragma unroll
        for (int it = 0; it < 2; it++) {
            int idx = tid + it * 256;
            int r = idx >> 5, c4 = (idx & 31) << 2;
            float4 v = *(const float4*)&B[(size_t)(k0 + r) * N + bn + c4];
            *(float4*)&Bs[r][c4] = v;
        }
        __syncthreads();

#pragma unroll
        for (int k = 0; k < BK; k++) {
            float a[8], b[8];
            *(float4*)&a[0] = *(const float4*)&As[k][ty * 8 + 0];
            *(float4*)&a[4] = *(const float4*)&As[k][ty * 8 + 4];
            *(float4*)&b[0] = *(const float4*)&Bs[k][tx * 8 + 0];
            *(float4*)&b[4] = *(const float4*)&Bs[k][tx * 8 + 4];
#pragma unroll
            for (int i = 0; i < 8; i++)
#pragma unroll
                for (int j = 0; j < 8; j++) acc[i][j] = fmaf(a[i], b[j], acc[i][j]);
        }
        __syncthreads();
    }

#pragma unroll
    for (int i = 0; i < 8; i++) {
        int row = bm + ty * 8 + i;
        if (row >= M) continue;
#pragma unroll
        for (int j4 = 0; j4 < 2; j4++) {
            int col = bn + tx * 8 + j4 * 4;
            float4 v;
            v.x = acc[i][j4 * 4 + 0]; v.y = acc[i][j4 * 4 + 1];
            v.z = acc[i][j4 * 4 + 2]; v.w = acc[i][j4 * 4 + 3];
            *(float4*)&C[(size_t)row * N + col] = v;
        }
    }
}

// ---------------------------------------------------------------------------
// Row norms: cn[row] = sum_k C[row,k]^2   (d = 1024)
// ---------------------------------------------------------------------------
__global__ __launch_bounds__(256)
void row_norm(const float* __restrict__ C, float* __restrict__ cn, int d)
{
    __shared__ float red[256];
    const int row = blockIdx.x;
    const float* c = C + (size_t)row * d;
    float s = 0.f;
    for (int j = threadIdx.x; j < d; j += 256) { float v = c[j]; s = fmaf(v, v, s); }
    red[threadIdx.x] = s; __syncthreads();
    for (int st = 128; st > 0; st >>= 1) {
        if (threadIdx.x < st) red[threadIdx.x] += red[threadIdx.x + st];
        __syncthreads();
    }
    if (threadIdx.x == 0) cn[row] = red[0];
}

// ---------------------------------------------------------------------------
// Row softmax of logits = 0.5*G - 0.25*cn, in place on G. cols <= 2048.
// One block of 256 threads per row.
// ---------------------------------------------------------------------------
__global__ __launch_bounds__(256)
void softmax_rows(float* __restrict__ G, const float* __restrict__ cn, int cols)
{
    __shared__ float red[256];
    const int row = blockIdx.x;
    float* g = G + (size_t)row * cols;
    const int tid = threadIdx.x;

    float l[8];
    float m = -1e30f;
    int cnt = 0;
    for (int j = tid; j < cols; j += 256) {
        float v = 0.5f * g[j] - 0.25f * cn[j];
        l[cnt++] = v;
        m = fmaxf(m, v);
    }
    red[tid] = m; __syncthreads();
    for (int st = 128; st > 0; st >>= 1) {
        if (tid < st) red[tid] = fmaxf(red[tid], red[tid + st]);
        __syncthreads();
    }
    m = red[0];
    __syncthreads();

    float s = 0.f;
    for (int c = 0; c < cnt; c++) { float e = expf(l[c] - m); l[c] = e; s += e; }
    red[tid] = s; __syncthreads();
    for (int st = 128; st > 0; st >>= 1) {
        if (tid < st) red[tid] += red[tid + st];
        __syncthreads();
    }
    float inv = 1.f / red[0];

    cnt = 0;
    for (int j = tid; j < cols; j += 256) g[j] = l[cnt++] * inv;
}

// ---------------------------------------------------------------------------
// Host orchestration
// ---------------------------------------------------------------------------
static void run_level(const float* h, int n_prev,
                      const float* centers, int n_cur,
                      const float* W, const float* b,
                      float* out, float* G, float* T, float* cn)
{
    // center norms
    row_norm<<<n_cur, 256>>>(centers, cn, D);
    // G = h @ centers^T
    {
        dim3 grid((n_cur + BN - 1) / BN, (n_prev + BM - 1) / BM);
        gemm_nt<0><<<grid, 256>>>(h, centers, nullptr, G, n_prev, n_cur, D);
    }
    // p = softmax rows (in place on G)
    softmax_rows<<<n_prev, 256>>>(G, cn, n_cur);
    // t = tanh(h @ W^T + b)
    {
        dim3 grid(D / BN, (n_prev + BM - 1) / BM);
        gemm_nt<1><<<grid, 256>>>(h, W, b, T, n_prev, D, D);
    }
    // out = p^T @ t
    {
        dim3 grid(D / BN, (n_cur + BM - 1) / BM);
        gemm_tn<<<grid, 256>>>(G, T, out, n_cur, D, n_prev);
    }
}

extern "C" void kernel_launch(void* const* d_in, const int* in_sizes, int n_in,
                              void* d_out, int out_size)
{
    const float* h0 = (const float*)d_in[0];
    const float* c1 = (const float*)d_in[1];
    const float* c2 = (const float*)d_in[2];
    const float* c3 = (const float*)d_in[3];
    const float* W1 = (const float*)d_in[4];
    const float* b1 = (const float*)d_in[5];
    const float* W2 = (const float*)d_in[6];
    const float* b2 = (const float*)d_in[7];
    const float* W3 = (const float*)d_in[8];
    const float* b3 = (const float*)d_in[9];
    float* out = (float*)d_out;

    float *pG, *pT, *pcn, *pH1, *pH2;
    cudaGetSymbolAddress((void**)&pG,  g_G);
    cudaGetSymbolAddress((void**)&pT,  g_T);
    cudaGetSymbolAddress((void**)&pcn, g_cn);
    cudaGetSymbolAddress((void**)&pH1, g_H1);
    cudaGetSymbolAddress((void**)&pH2, g_H2);

    run_level(h0,  N0, c1, N1, W1, b1, pH1, pG, pT, pcn);
    run_level(pH1, N1, c2, N2, W2, b2, pH2, pG, pT, pcn);
    run_level(pH2, N2, c3, N3, W3, b3, out, pG, pT, pcn);
}

// round 2
// speedup vs baseline: 2.3429x; 2.3429x over previous
#include <cuda_runtime.h>
#include <cuda_bf16.h>
#include <math.h>

// ---------------------------------------------------------------------------
// HierarchicalClustering via split-bf16 tensor-core GEMMs.
//   logits = 0.5*(h @ c^T) - 0.25*||c||^2   (||h||^2 cancels in softmax)
//   p      = softmax_rows(logits)
//   t      = tanh(h @ W^T + b)
//   h_next = p^T @ t
// All GEMMs: C = A @ B^T with A,B given as bf16 (hi,lo) pair-packed arrays
// [rows][K/2] (u32 = {bf16 even-k, bf16 odd-k}), computed as
// hi*hi + hi*lo + lo*hi with fp32 accumulation (mma.m16n8k16.bf16).
// ---------------------------------------------------------------------------

#define D 1024
#define N0 16384
#define N1 2048
#define N2 256
#define N3 32

// ------------------------- scratch (device globals) ------------------------
__device__ float    g_G[(size_t)N0 * N1];            // logits / p (fp32)
__device__ float    g_cn[N1];                        // center norms
__device__ float    g_Hn[(size_t)N1 * D];            // h_next fp32
__device__ unsigned g_hPhi[(size_t)N0 * (D / 2)];    // h pairs
__device__ unsigned g_hPlo[(size_t)N0 * (D / 2)];
__device__ unsigned g_cPhi[(size_t)N1 * (D / 2)];    // centers pairs
__device__ unsigned g_cPlo[(size_t)N1 * (D / 2)];
__device__ unsigned g_wPhi[(size_t)D * (D / 2)];     // W pairs
__device__ unsigned g_wPlo[(size_t)D * (D / 2)];
__device__ unsigned g_GThi[(size_t)N1 * (N0 / 2)];   // p^T pairs
__device__ unsigned g_GTlo[(size_t)N1 * (N0 / 2)];
__device__ unsigned g_tThi[(size_t)D * (N0 / 2)];    // t^T pairs
__device__ unsigned g_tTlo[(size_t)D * (N0 / 2)];

// ------------------------------- helpers -----------------------------------
__device__ __forceinline__ unsigned bf16_hi_bits(float v, float& rem) {
    __nv_bfloat16 h = __float2bfloat16_rn(v);
    rem = v - __bfloat162float(h);
    return (unsigned)*reinterpret_cast<unsigned short*>(&h);
}
__device__ __forceinline__ unsigned bf16_bits(float v) {
    __nv_bfloat16 h = __float2bfloat16_rn(v);
    return (unsigned)*reinterpret_cast<unsigned short*>(&h);
}

// split-pack: X fp32 [n*2 elems] -> hi/lo pair arrays (u32 per 2 elems)
__global__ __launch_bounds__(256)
void split_pack(const float* __restrict__ X, unsigned* __restrict__ hi,
                unsigned* __restrict__ lo, size_t npairs)
{
    size_t i = (size_t)blockIdx.x * 256 + threadIdx.x;
    if (i >= npairs) return;
    float2 v = reinterpret_cast<const float2*>(X)[i];
    float ra, rb;
    unsigned ha = bf16_hi_bits(v.x, ra);
    unsigned hb = bf16_hi_bits(v.y, rb);
    hi[i] = ha | (hb << 16);
    lo[i] = bf16_bits(ra) | (bf16_bits(rb) << 16);
}

// transpose + split: G [R][C] fp32 -> GT hi/lo [C][R/2] pairs along R
__global__ __launch_bounds__(256)
void transpose_split(const float* __restrict__ G, unsigned* __restrict__ hi,
                     unsigned* __restrict__ lo, int R, int C)
{
    __shared__ float tile[32][33];
    const int r0 = blockIdx.x * 32, c0 = blockIdx.y * 32;
    const int tid = threadIdx.x;
    for (int i = tid; i < 1024; i += 256) {
        int rl = i >> 5, cl = i & 31;
        tile[cl][rl] = G[(size_t)(r0 + rl) * C + c0 + cl];
    }
    __syncthreads();
    for (int i = tid; i < 512; i += 256) {
        int cl = i >> 4, p = i & 15;
        float a = tile[cl][2 * p], b = tile[cl][2 * p + 1];
        float ra, rb;
        unsigned ha = bf16_hi_bits(a, ra);
        unsigned hb = bf16_hi_bits(b, rb);
        size_t o = (size_t)(c0 + cl) * (size_t)(R >> 1) + (r0 >> 1) + p;
        hi[o] = ha | (hb << 16);
        lo[o] = bf16_bits(ra) | (bf16_bits(rb) << 16);
    }
}

// row norms: cn[row] = sum_k C[row,k]^2  (d = 1024)
__global__ __launch_bounds__(256)
void row_norm(const float* __restrict__ C, float* __restrict__ cn, int d)
{
    __shared__ float red[256];
    const int row = blockIdx.x;
    const float* c = C + (size_t)row * d;
    float s = 0.f;
    for (int j = threadIdx.x; j < d; j += 256) { float v = c[j]; s = fmaf(v, v, s); }
    red[threadIdx.x] = s; __syncthreads();
    for (int st = 128; st > 0; st >>= 1) {
        if (threadIdx.x < st) red[threadIdx.x] += red[threadIdx.x + st];
        __syncthreads();
    }
    if (threadIdx.x == 0) cn[row] = red[0];
}

// row softmax of logits = 0.5*G - 0.25*cn, in place on G. cols <= 2048.
__global__ __launch_bounds__(256)
void softmax_rows(float* __restrict__ G, const float* __restrict__ cn, int cols)
{
    __shared__ float red[256];
    const int row = blockIdx.x;
    float* g = G + (size_t)row * cols;
    const int tid = threadIdx.x;

    float l[8];
    float m = -1e30f;
    int cnt = 0;
    for (int j = tid; j < cols; j += 256) {
        float v = 0.5f * g[j] - 0.25f * cn[j];
        l[cnt++] = v;
        m = fmaxf(m, v);
    }
    red[tid] = m; __syncthreads();
    for (int st = 128; st > 0; st >>= 1) {
        if (tid < st) red[tid] = fmaxf(red[tid], red[tid + st]);
        __syncthreads();
    }
    m = red[0];
    __syncthreads();

    float s = 0.f;
    for (int c = 0; c < cnt; c++) { float e = expf(l[c] - m); l[c] = e; s += e; }
    red[tid] = s; __syncthreads();
    for (int st = 128; st > 0; st >>= 1) {
        if (tid < st) red[tid] += red[tid + st];
        __syncthreads();
    }
    float inv = 1.f / red[0];

    cnt = 0;
    for (int j = tid; j < cols; j += 256) g[j] = l[cnt++] * inv;
}

// ---------------------------------------------------------------------------
// split-3 bf16 tensor GEMM: C[M,N] = A[M,K] * B[N,K]^T, fp32 accumulate.
// A,B as pair-packed hi/lo u32 arrays [rows][K/2].
// EPI 0: fp32 store to C (row/col guarded).
// EPI 1: v = tanh(acc + bias[col]); write v transposed+split to Thi/Tlo
//        [N rows][M/2 pair cols]  (requires M%128==0, N%128==0).
// ---------------------------------------------------------------------------
#define BM 128
#define BN 128
#define BK 32
#define KPT 16        // u32 pairs per tile row
#define TSTR 20       // padded smem row stride (u32)
#define TILE_U32 (128 * TSTR)

__device__ __forceinline__ void mma_bf16(float* c, const unsigned* a, const unsigned* b)
{
    asm volatile(
        "mma.sync.aligned.m16n8k16.row.col.f32.bf16.bf16.f32 "
        "{%0,%1,%2,%3}, {%4,%5,%6,%7}, {%8,%9}, {%0,%1,%2,%3};"
        : "+f"(c[0]), "+f"(c[1]), "+f"(c[2]), "+f"(c[3])
        : "r"(a[0]), "r"(a[1]), "r"(a[2]), "r"(a[3]), "r"(b[0]), "r"(b[1]));
}

__device__ __forceinline__ void cpa16(unsigned dst, const void* src, bool pred)
{
    int sz = pred ? 16 : 0;
    asm volatile("cp.async.ca.shared.global [%0], [%1], 16, %2;\n"
                 :: "r"(dst), "l"(src), "r"(sz));
}

template <int EPI>
__global__ __launch_bounds__(256)
void gemm3(const unsigned* __restrict__ Ahi, const unsigned* __restrict__ Alo,
           const unsigned* __restrict__ Bhi, const unsigned* __restrict__ Blo,
           const float* __restrict__ bias, float* __restrict__ C,
           unsigned* __restrict__ Thi, unsigned* __restrict__ Tlo,
           int M, int N, int K)
{
    extern __shared__ __align__(16) unsigned dynbuf[];
    const int tid  = threadIdx.x;
    const int bm   = blockIdx.y * BM, bn = blockIdx.x * BN;
    const int KPg  = K >> 1;
    const int lane = tid & 31, wid = tid >> 5;
    const int wr   = (wid >> 2) * 64, wc = (wid & 3) * 32;
    const int g    = lane >> 2, t = lane & 3;

    float acc[4][4][4];
#pragma unroll
    for (int mi = 0; mi < 4; mi++)
#pragma unroll
        for (int ni = 0; ni < 4; ni++)
#pragma unroll
            for (int k = 0; k < 4; k++) acc[mi][ni][k] = 0.f;

    const int NIT = K / BK;
    const unsigned sbase = (unsigned)__cvta_generic_to_shared(dynbuf);

    auto prefetch = [&](int it, int s) {
        const int kp0 = it * KPT;
        const unsigned stg = sbase + (unsigned)s * (4 * TILE_U32 * 4);
#pragma unroll
        for (int h = 0; h < 2; h++) {
            int c = tid + h * 256;           // 0..511
            int row = c >> 2, seg = (c & 3) << 2;
            unsigned soff = (unsigned)(row * TSTR + seg) * 4;
            bool pa = (bm + row) < M;
            bool pb = (bn + row) < N;
            size_t ga = (size_t)(pa ? bm + row : 0) * KPg + kp0 + seg;
            size_t gb = (size_t)(pb ? bn + row : 0) * KPg + kp0 + seg;
            cpa16(stg + 0 * TILE_U32 * 4 + soff, Ahi + ga, pa);
            cpa16(stg + 1 * TILE_U32 * 4 + soff, Alo + ga, pa);
            cpa16(stg + 2 * TILE_U32 * 4 + soff, Bhi + gb, pb);
            cpa16(stg + 3 * TILE_U32 * 4 + soff, Blo + gb, pb);
        }
    };

    prefetch(0, 0);
    asm volatile("cp.async.commit_group;\n");

    for (int it = 0; it < NIT; ++it) {
        const int s = it & 1;
        if (it + 1 < NIT) {
            prefetch(it + 1, s ^ 1);
            asm volatile("cp.async.commit_group;\n");
            asm volatile("cp.async.wait_group 1;\n");
        } else {
            asm volatile("cp.async.wait_group 0;\n");
        }
        __syncthreads();

        const unsigned* As_hi = dynbuf + (s * 4 + 0) * TILE_U32;
        const unsigned* As_lo = dynbuf + (s * 4 + 1) * TILE_U32;
        const unsigned* Bs_hi = dynbuf + (s * 4 + 2) * TILE_U32;
        const unsigned* Bs_lo = dynbuf + (s * 4 + 3) * TILE_U32;

#pragma unroll
        for (int ks = 0; ks < 2; ks++) {
            const int kp = ks * 8;
            unsigned ah[4][4], al[4][4], bh[4][2], bl[4][2];
#pragma unroll
            for (int mi = 0; mi < 4; mi++) {
                int r = wr + mi * 16 + g;
                ah[mi][0] = As_hi[r * TSTR + kp + t];
                ah[mi][1] = As_hi[(r + 8) * TSTR + kp + t];
                ah[mi][2] = As_hi[r * TSTR + kp + t + 4];
                ah[mi][3] = As_hi[(r + 8) * TSTR + kp + t + 4];
                al[mi][0] = As_lo[r * TSTR + kp + t];
                al[mi][1] = As_lo[(r + 8) * TSTR + kp + t];
                al[mi][2] = As_lo[r * TSTR + kp + t + 4];
                al[mi][3] = As_lo[(r + 8) * TSTR + kp + t + 4];
            }
#pragma unroll
            for (int ni = 0; ni < 4; ni++) {
                int cc = wc + ni * 8 + g;
                bh[ni][0] = Bs_hi[cc * TSTR + kp + t];
                bh[ni][1] = Bs_hi[cc * TSTR + kp + t + 4];
                bl[ni][0] = Bs_lo[cc * TSTR + kp + t];
                bl[ni][1] = Bs_lo[cc * TSTR + kp + t + 4];
            }
#pragma unroll
            for (int mi = 0; mi < 4; mi++)
#pragma unroll
                for (int ni = 0; ni < 4; ni++) {
                    mma_bf16(acc[mi][ni], ah[mi], bh[ni]);
                    mma_bf16(acc[mi][ni], ah[mi], bl[ni]);
                    mma_bf16(acc[mi][ni], al[mi], bh[ni]);
                }
        }
        __syncthreads();
    }

    if (EPI == 0) {
#pragma unroll
        for (int mi = 0; mi < 4; mi++) {
            int r = bm + wr + mi * 16 + g;
#pragma unroll
            for (int ni = 0; ni < 4; ni++) {
                int cc = bn + wc + ni * 8 + 2 * t;
                if (cc < N) {
                    if (r < M)
                        *reinterpret_cast<float2*>(&C[(size_t)r * N + cc]) =
                            make_float2(acc[mi][ni][0], acc[mi][ni][1]);
                    if (r + 8 < M)
                        *reinterpret_cast<float2*>(&C[(size_t)(r + 8) * N + cc]) =
                            make_float2(acc[mi][ni][2], acc[mi][ni][3]);
                }
            }
        }
    } else {
        // tanh + write transposed split pairs: T[n][m/2]
        const size_t Mh = (size_t)(M >> 1);
#pragma unroll
        for (int mi = 0; mi < 4; mi++) {
            int mglob = bm + wr + mi * 16 + g;        // row of v0/v1; +8 for v2/v3
#pragma unroll
            for (int ni = 0; ni < 4; ni++) {
                int cc = bn + wc + ni * 8 + 2 * t;
                float b0 = bias[cc], b1 = bias[cc + 1];
                float v[4];
                v[0] = tanhf(acc[mi][ni][0] + b0);
                v[1] = tanhf(acc[mi][ni][1] + b1);
                v[2] = tanhf(acc[mi][ni][2] + b0);
                v[3] = tanhf(acc[mi][ni][3] + b1);
#pragma unroll
                for (int vi = 0; vi < 4; vi++) {
                    float rem;
                    unsigned hb = bf16_hi_bits(v[vi], rem);
                    unsigned lb = bf16_bits(rem);
                    unsigned pkt = hb | (lb << 16);
                    unsigned oth = __shfl_xor_sync(0xffffffffu, pkt, 4);
                    if ((lane & 4) == 0) {
                        unsigned hi_u = (pkt & 0xffffu) | ((oth & 0xffffu) << 16);
                        unsigned lo_u = (pkt >> 16) | (oth & 0xffff0000u);
                        int n = cc + (vi & 1);
                        int mp = ((mglob + ((vi >> 1) << 3)) >> 1);
                        size_t off = (size_t)n * Mh + mp;
                        Thi[off] = hi_u;
                        Tlo[off] = lo_u;
                    }
                }
            }
        }
    }
}

// ---------------------------------------------------------------------------
// Host orchestration
// ---------------------------------------------------------------------------
#define SMEM_BYTES (2 * 4 * TILE_U32 * 4)

static void run_level(const float* h_fp32, unsigned* hPhi, unsigned* hPlo,
                      const float* centers, const float* W, const float* b,
                      int n_prev, int n_cur,
                      unsigned* cPhi, unsigned* cPlo,
                      unsigned* wPhi, unsigned* wPlo,
                      float* G, float* cn,
                      unsigned* GThi, unsigned* GTlo,
                      unsigned* tThi, unsigned* tTlo,
                      float* out)
{
    // pack inputs
    {
        size_t np = (size_t)n_prev * (D / 2);
        split_pack<<<(unsigned)((np + 255) / 256), 256>>>(h_fp32, hPhi, hPlo, np);
        np = (size_t)n_cur * (D / 2);
        split_pack<<<(unsigned)((np + 255) / 256), 256>>>(centers, cPhi, cPlo, np);
        np = (size_t)D * (D / 2);
        split_pack<<<(unsigned)((np + 255) / 256), 256>>>(W, wPhi, wPlo, np);
    }
    row_norm<<<n_cur, 256>>>(centers, cn, D);

    // G = h @ c^T
    {
        dim3 grid((n_cur + BN - 1) / BN, (n_prev + BM - 1) / BM);
        gemm3<0><<<grid, 256, SMEM_BYTES>>>(hPhi, hPlo, cPhi, cPlo, nullptr, G,
                                            nullptr, nullptr, n_prev, n_cur, D);
    }
    softmax_rows<<<n_prev, 256>>>(G, cn, n_cur);
    transpose_split<<<dim3(n_prev / 32, (n_cur + 31) / 32), 256>>>(G, GThi, GTlo,
                                                                   n_prev, n_cur);
    // t = tanh(h @ W^T + b), written transposed+split
    {
        dim3 grid(D / BN, n_prev / BM);
        gemm3<1><<<grid, 256, SMEM_BYTES>>>(hPhi, hPlo, wPhi, wPlo, b, nullptr,
                                            tThi, tTlo, n_prev, D, D);
    }
    // out = p^T @ t  (pure NT on the transposed pair arrays)
    {
        dim3 grid(D / BN, (n_cur + BM - 1) / BM);
        gemm3<0><<<grid, 256, SMEM_BYTES>>>(GThi, GTlo, tThi, tTlo, nullptr, out,
                                            nullptr, nullptr, n_cur, D, n_prev);
    }
}

extern "C" void kernel_launch(void* const* d_in, const int* in_sizes, int n_in,
                              void* d_out, int out_size)
{
    const float* h0 = (const float*)d_in[0];
    const float* c1 = (const float*)d_in[1];
    const float* c2 = (const float*)d_in[2];
    const float* c3 = (const float*)d_in[3];
    const float* W1 = (const float*)d_in[4];
    const float* b1 = (const float*)d_in[5];
    const float* W2 = (const float*)d_in[6];
    const float* b2 = (const float*)d_in[7];
    const float* W3 = (const float*)d_in[8];
    const float* b3 = (const float*)d_in[9];
    float* out = (float*)d_out;

    cudaFuncSetAttribute(gemm3<0>, cudaFuncAttributeMaxDynamicSharedMemorySize, SMEM_BYTES);
    cudaFuncSetAttribute(gemm3<1>, cudaFuncAttributeMaxDynamicSharedMemorySize, SMEM_BYTES);

    float *pG, *pcn, *pHn;
    unsigned *hPhi, *hPlo, *cPhi, *cPlo, *wPhi, *wPlo, *GThi, *GTlo, *tThi, *tTlo;
    cudaGetSymbolAddress((void**)&pG,   g_G);
    cudaGetSymbolAddress((void**)&pcn,  g_cn);
    cudaGetSymbolAddress((void**)&pHn,  g_Hn);
    cudaGetSymbolAddress((void**)&hPhi, g_hPhi);
    cudaGetSymbolAddress((void**)&hPlo, g_hPlo);
    cudaGetSymbolAddress((void**)&cPhi, g_cPhi);
    cudaGetSymbolAddress((void**)&cPlo, g_cPlo);
    cudaGetSymbolAddress((void**)&wPhi, g_wPhi);
    cudaGetSymbolAddress((void**)&wPlo, g_wPlo);
    cudaGetSymbolAddress((void**)&GThi, g_GThi);
    cudaGetSymbolAddress((void**)&GTlo, g_GTlo);
    cudaGetSymbolAddress((void**)&tThi, g_tThi);
    cudaGetSymbolAddress((void**)&tTlo, g_tTlo);

    // Level 1: 16384 -> 2048
    run_level(h0, hPhi, hPlo, c1, W1, b1, N0, N1,
              cPhi, cPlo, wPhi, wPlo, pG, pcn, GThi, GTlo, tThi, tTlo, pHn);
    // Level 2: 2048 -> 256
    run_level(pHn, hPhi, hPlo, c2, W2, b2, N1, N2,
              cPhi, cPlo, wPhi, wPlo, pG, pcn, GThi, GTlo, tThi, tTlo, pHn);
    // Level 3: 256 -> 32 (final output fp32 to d_out)
    run_level(pHn, hPhi, hPlo, c3, W3, b3, N2, N3,
              cPhi, cPlo, wPhi, wPlo, pG, pcn, GThi, GTlo, tThi, tTlo, out);
}